// round 9
// baseline (speedup 1.0000x reference)
#include <cuda_runtime.h>
#include <cstdint>

// ============================================================================
// out[8192,512] = feats @ W^T + bias,  feats[b] = [x (128), x_i*x_j i<=j (8256)]
// K = 8384.  INT8 IMMA limb GEMM:
//   f = a1*2^-1 + a2*2^-8 + a3*2^-15   (exact, residual <= 2^-16)
//   w = b1*2^-4 + b2*2^-11             (exact, residual <= 2^-12)
//   out = 2^-5*ACC(a1b1) + 2^-12*ACC(a1b2+a2b1) + 2^-19*ACC(a2b2+a3b1)
// ============================================================================
static constexpr int DIM    = 128;
static constexpr int NQUAD  = 8256;
static constexpr int NFEAT  = 8384;
static constexpr int BATCH  = 8192;
static constexpr int NOUT   = 512;
static constexpr int KPW4   = NFEAT / 4;          // 2096 words per W row (s8 packed)

static constexpr int TM = 64;
static constexpr int TN = 128;
static constexpr int TK = 64;                     // 64 s8 = 16 words per row
static constexpr int NKT = NFEAT / TK;            // 131
static constexpr int NSTG = 3;
static constexpr int THREADS = 640;               // 16 consumer + 4 producer warps
static constexpr int NCONS   = 512;

static constexpr int STRW = 20;                   // row pitch in words (16 data + pad)

// SMEM layout (words)
static constexpr int XT_OFF    = 0;               // fp32 x^T: 128 cols x 68
static constexpr int XT_STRIDE = 68;
static constexpr int AW_OFF  = XT_OFF + DIM * XT_STRIDE;   // 8704
static constexpr int A_PLANE = TM * STRW;                   // 1280
static constexpr int A_STAGE = 3 * A_PLANE;                 // 3840
static constexpr int BW_OFF  = AW_OFF + NSTG * A_STAGE;     // 20224
static constexpr int B_PLANE = TN * STRW;                   // 2560
static constexpr int B_STAGE = 2 * B_PLANE;                 // 5120
static constexpr int BIAS_OFF = BW_OFF + NSTG * B_STAGE;    // 35584
static constexpr int SMEM_WORDS = BIAS_OFF + TN;            // 35712
static constexpr int SMEM_BYTES = SMEM_WORDS * 4;           // 142848

// Named barriers: full[s] = 1..3, empty[s] = 4..6
#define BAR_SYNC(id)   asm volatile("bar.sync %0, %1;"   :: "r"(id), "r"(THREADS) : "memory")
#define BAR_ARRIVE(id) asm volatile("bar.arrive %0, %1;" :: "r"(id), "r"(THREADS) : "memory")

// ============================================================================
// Device scratch: W limb planes (s8 packed in words) + pair LUT
// ============================================================================
__device__ __align__(16) uint32_t g_wb1[NOUT * KPW4];   // 4.29 MB
__device__ __align__(16) uint32_t g_wb2[NOUT * KPW4];   // 4.29 MB
__device__ __align__(16) unsigned short g_pairs[NQUAD];

__device__ __forceinline__ int pair_off(int i) { return DIM * i - (i * (i - 1)) / 2; }

__device__ __forceinline__ uint32_t pack4(int a0, int a1, int a2, int a3) {
    return (uint32_t)(a0 & 0xFF) | ((uint32_t)(a1 & 0xFF) << 8) |
           ((uint32_t)(a2 & 0xFF) << 16) | ((uint32_t)a3 << 24);
}

__global__ void init_kernel(const float* __restrict__ w) {
    int gidx = blockIdx.x * 256 + threadIdx.x;
    if (gidx < NQUAD) {
        int q = gidx;
        int i = (int)((257.0f - sqrtf(66049.0f - 8.0f * (float)q)) * 0.5f);
        if (i < 0) i = 0;
        if (i > DIM - 1) i = DIM - 1;
        while (i > 0 && pair_off(i) > q) i--;
        while (i < DIM - 1 && pair_off(i + 1) <= q) i++;
        int j = i + (q - pair_off(i));
        g_pairs[q] = (unsigned short)((i << 8) | j);
    }
    int total = NOUT * KPW4;
    for (int idx = gidx; idx < total; idx += gridDim.x * 256) {
        float4 v = *reinterpret_cast<const float4*>(w + 4 * (size_t)idx);
        int b1[4], b2[4];
        float vv[4] = {v.x, v.y, v.z, v.w};
#pragma unroll
        for (int e = 0; e < 4; e++) {
            b1[e] = __float2int_rn(vv[e] * 16.0f);
            float r = fmaf((float)b1[e], -0.0625f, vv[e]);
            b2[e] = __float2int_rn(r * 2048.0f);
        }
        g_wb1[idx] = pack4(b1[0], b1[1], b1[2], b1[3]);
        g_wb2[idx] = pack4(b2[0], b2[1], b2[2], b2[3]);
    }
}

// ============================================================================
// helpers
// ============================================================================
__device__ __forceinline__ uint32_t smem_u32(const void* p) {
    uint32_t a;
    asm("{ .reg .u64 t; cvta.to.shared.u64 t, %1; cvt.u32.u64 %0, t; }" : "=r"(a) : "l"(p));
    return a;
}
__device__ __forceinline__ void cp_async16(uint32_t dst, const void* src) {
    asm volatile("cp.async.cg.shared.global [%0], [%1], 16;" :: "r"(dst), "l"(src) : "memory");
}
__device__ __forceinline__ void cp_commit() { asm volatile("cp.async.commit_group;" ::: "memory"); }
template <int N>
__device__ __forceinline__ void cp_wait() { asm volatile("cp.async.wait_group %0;" :: "n"(N) : "memory"); }

__device__ __forceinline__ void ldsm_x4(uint32_t& r0, uint32_t& r1, uint32_t& r2,
                                        uint32_t& r3, uint32_t addr) {
    asm volatile("ldmatrix.sync.aligned.m8n8.x4.shared.b16 {%0,%1,%2,%3}, [%4];"
                 : "=r"(r0), "=r"(r1), "=r"(r2), "=r"(r3) : "r"(addr));
}

__device__ __forceinline__ void imma(int d[4], const uint32_t a[4], const uint32_t b[2]) {
    asm volatile(
        "mma.sync.aligned.m16n8k32.row.col.s32.s8.s8.s32 "
        "{%0,%1,%2,%3}, {%4,%5,%6,%7}, {%8,%9}, {%0,%1,%2,%3};"
        : "+r"(d[0]), "+r"(d[1]), "+r"(d[2]), "+r"(d[3])
        : "r"(a[0]), "r"(a[1]), "r"(a[2]), "r"(a[3]), "r"(b[0]), "r"(b[1]));
}

// ============================================================================
// Fused polynomial-feature GEMM (int8 limb IMMA, warp-specialized, 3 stages)
// ============================================================================
__global__ void __launch_bounds__(THREADS, 1)
poly_gemm_kernel(const float* __restrict__ x,
                 const float* __restrict__ bias,
                 float* __restrict__ out) {
    extern __shared__ float smemf[];
    uint32_t* smemw = reinterpret_cast<uint32_t*>(smemf);
    float* XT = smemf + XT_OFF;
    const uint32_t sb = smem_u32(smemf);

    const int tid  = threadIdx.x;
    const int lane = tid & 31;
    const int warp = tid >> 5;

    const int m0 = (int)(blockIdx.x >> 2) * TM;   // 128 M tiles
    const int n0 = (int)(blockIdx.x & 3) * TN;    // 4   N tiles

    // ---------------- prologue: xT tile + bias ----------------
    for (int idx = tid; idx < TM * DIM; idx += THREADS) {
        int r = idx & 63, c = idx >> 6;
        XT[c * XT_STRIDE + r] = x[(size_t)(m0 + r) * DIM + c];
    }
    if (tid < TN) smemf[BIAS_OFF + tid] = bias[n0 + tid];
    __syncthreads();

    if (warp >= 16) {
        // =================== PRODUCER (4 warps) ===================
        const int pid = tid - NCONS;        // 0..127
        const int kq  = pid & 7;            // k-octet within 64-K tile
        const int r0  = (pid >> 3) * 4;     // 4 rows per thread

#pragma unroll 1
        for (int t = 0; t < NKT; ++t) {
            int s = t % NSTG;
            if (t >= NSTG) BAR_SYNC(4 + s);

            // ---- B limbs via cp.async: 8 x 16B per thread ----
            {
                uint32_t dst0 = sb + (uint32_t)(BW_OFF + s * B_STAGE) * 4u;
#pragma unroll
                for (int i = 0; i < 8; i++) {
                    int c     = pid + i * 128;      // 0..1023
                    int plane = c >> 9;
                    int cc    = c & 511;
                    int row   = cc >> 2, qw = cc & 3;
                    const uint32_t* src = (plane ? g_wb2 : g_wb1)
                                        + (size_t)(n0 + row) * KPW4 + t * 16 + qw * 4;
                    cp_async16(dst0 + (uint32_t)(plane * B_PLANE + row * STRW + qw * 4) * 4u, src);
                }
                cp_commit();
            }

            // ---- A limbs: 8 k x 4 rows per thread ----
            {
                int kg = t * TK + kq * 8;
                float f[8][4];
                if (kg < DIM) {
#pragma unroll
                    for (int kk = 0; kk < 8; kk++) {
                        float4 v = *(const float4*)(XT + (kg + kk) * XT_STRIDE + r0);
                        f[kk][0] = v.x; f[kk][1] = v.y; f[kk][2] = v.z; f[kk][3] = v.w;
                    }
                } else {
                    uint4 pw = *reinterpret_cast<const uint4*>(&g_pairs[kg - DIM]);
                    uint32_t wv[4] = {pw.x, pw.y, pw.z, pw.w};
#pragma unroll
                    for (int h = 0; h < 4; h++) {
                        uint32_t u = wv[h];
                        int i0 = (u >> 8) & 255,  j0 = u & 255;
                        int i1 = (u >> 24) & 255, j1 = (u >> 16) & 255;
                        float4 xa = *(const float4*)(XT + i0 * XT_STRIDE + r0);
                        float4 xb = *(const float4*)(XT + j0 * XT_STRIDE + r0);
                        float4 xc = *(const float4*)(XT + i1 * XT_STRIDE + r0);
                        float4 xd = *(const float4*)(XT + j1 * XT_STRIDE + r0);
                        f[2*h+0][0] = xa.x*xb.x; f[2*h+0][1] = xa.y*xb.y;
                        f[2*h+0][2] = xa.z*xb.z; f[2*h+0][3] = xa.w*xb.w;
                        f[2*h+1][0] = xc.x*xd.x; f[2*h+1][1] = xc.y*xd.y;
                        f[2*h+1][2] = xc.z*xd.z; f[2*h+1][3] = xc.w*xd.w;
                    }
                }
                uint32_t a_stage = (uint32_t)(AW_OFF + s * A_STAGE);
#pragma unroll
                for (int r = 0; r < 4; r++) {
                    int a1[8], a2[8], a3[8];
#pragma unroll
                    for (int kk = 0; kk < 8; kk++) {
                        float v = f[kk][r];
                        a1[kk] = __float2int_rn(v * 2.0f);
                        float r1 = fmaf((float)a1[kk], -0.5f, v);
                        a2[kk] = __float2int_rn(r1 * 256.0f);
                        float r2 = fmaf((float)a2[kk], -0.00390625f, r1);
                        a3[kk] = __float2int_rn(r2 * 32768.0f);
                    }
                    uint32_t wo = (uint32_t)((r0 + r) * STRW + kq * 2);
                    uint2 w1 = { pack4(a1[0],a1[1],a1[2],a1[3]), pack4(a1[4],a1[5],a1[6],a1[7]) };
                    uint2 w2 = { pack4(a2[0],a2[1],a2[2],a2[3]), pack4(a2[4],a2[5],a2[6],a2[7]) };
                    uint2 w3 = { pack4(a3[0],a3[1],a3[2],a3[3]), pack4(a3[4],a3[5],a3[6],a3[7]) };
                    *reinterpret_cast<uint2*>(smemw + a_stage + wo)               = w1;
                    *reinterpret_cast<uint2*>(smemw + a_stage + A_PLANE + wo)     = w2;
                    *reinterpret_cast<uint2*>(smemw + a_stage + 2 * A_PLANE + wo) = w3;
                }
            }

            cp_wait<0>();
            BAR_ARRIVE(1 + s);
        }
    } else {
        // =================== CONSUMER (16 warps) ===================
        const int mw = warp >> 2;           // 0..3  rows mw*16
        const int nw = warp & 3;            // 0..3  cols nw*32

        int acc0[4][4], acc1[4][4], acc2[4][4];
#pragma unroll
        for (int n = 0; n < 4; n++)
#pragma unroll
            for (int c = 0; c < 4; c++) { acc0[n][c] = 0; acc1[n][c] = 0; acc2[n][c] = 0; }

        const int a_lane_w = (lane & 15) * STRW + (lane >> 4) * 4;
        const int b_lane_w = ((lane & 7) + ((lane >> 4) & 1) * 8) * STRW + ((lane >> 3) & 1) * 4;

#pragma unroll 1
        for (int t = 0; t < NKT; ++t) {
            int s = t % NSTG;
            BAR_SYNC(1 + s);

            const uint32_t a_base = sb + (uint32_t)(AW_OFF + s * A_STAGE
                                    + (mw * 16) * STRW + a_lane_w) * 4u;
            const uint32_t b_base = sb + (uint32_t)(BW_OFF + s * B_STAGE
                                    + (nw * 32) * STRW + b_lane_w) * 4u;
#pragma unroll
            for (int ks = 0; ks < 2; ks++) {        // two k32 chunks
                uint32_t ua1[4], ua2[4], ua3[4];
                uint32_t ap = a_base + (uint32_t)(ks * 8) * 4u;
                ldsm_x4(ua1[0], ua1[1], ua1[2], ua1[3], ap);
                ldsm_x4(ua2[0], ua2[1], ua2[2], ua2[3], ap + (uint32_t)A_PLANE * 4u);
                ldsm_x4(ua3[0], ua3[1], ua3[2], ua3[3], ap + (uint32_t)(2 * A_PLANE) * 4u);

                uint32_t ub1[4][2], ub2[4][2];
#pragma unroll
                for (int p = 0; p < 2; p++) {       // each ldsm covers 2 n-tiles
                    uint32_t bp = b_base + (uint32_t)(p * 16 * STRW + ks * 8) * 4u;
                    ldsm_x4(ub1[2*p][0], ub1[2*p][1], ub1[2*p+1][0], ub1[2*p+1][1], bp);
                    ldsm_x4(ub2[2*p][0], ub2[2*p][1], ub2[2*p+1][0], ub2[2*p+1][1],
                            bp + (uint32_t)B_PLANE * 4u);
                }
#pragma unroll
                for (int n = 0; n < 4; n++) imma(acc0[n], ua1, ub1[n]);
#pragma unroll
                for (int n = 0; n < 4; n++) imma(acc1[n], ua1, ub2[n]);
#pragma unroll
                for (int n = 0; n < 4; n++) imma(acc1[n], ua2, ub1[n]);
#pragma unroll
                for (int n = 0; n < 4; n++) imma(acc2[n], ua2, ub2[n]);
#pragma unroll
                for (int n = 0; n < 4; n++) imma(acc2[n], ua3, ub1[n]);
            }
            BAR_ARRIVE(4 + s);
        }

        // ---------------- epilogue: combine scales + bias ----------------
        const float S0 = 0.03125f;            // 2^-5
        const float S1 = 2.44140625e-4f;      // 2^-12
        const float S2 = 1.9073486328125e-6f; // 2^-19
#pragma unroll
        for (int n = 0; n < 4; n++) {
            int colb = nw * 32 + n * 8 + (lane & 3) * 2;
            float bx = smemf[BIAS_OFF + colb];
            float by = smemf[BIAS_OFF + colb + 1];
#pragma unroll
            for (int half = 0; half < 2; half++) {
                int row = m0 + mw * 16 + (lane >> 2) + half * 8;
                float2 o;
                o.x = fmaf((float)acc0[n][2*half+0], S0,
                      fmaf((float)acc1[n][2*half+0], S1,
                           (float)acc2[n][2*half+0] * S2)) + bx;
                o.y = fmaf((float)acc0[n][2*half+1], S0,
                      fmaf((float)acc1[n][2*half+1], S1,
                           (float)acc2[n][2*half+1] * S2)) + by;
                *(float2*)(out + (size_t)row * NOUT + n0 + colb) = o;
            }
        }
    }
}

// ============================================================================
// Host launch
// ============================================================================
extern "C" void kernel_launch(void* const* d_in, const int* in_sizes, int n_in,
                              void* d_out, int out_size) {
    const float* x    = (const float*)d_in[0];
    const float* w    = (const float*)d_in[1];
    const float* bias = (const float*)d_in[2];
    float* out        = (float*)d_out;

    cudaFuncSetAttribute(poly_gemm_kernel,
                         cudaFuncAttributeMaxDynamicSharedMemorySize, SMEM_BYTES);

    init_kernel<<<1184, 256>>>(w);
    poly_gemm_kernel<<<(BATCH / TM) * (NOUT / TN), THREADS, SMEM_BYTES>>>(x, bias, out);
}

// round 10
// speedup vs baseline: 3.1571x; 3.1571x over previous
#include <cuda_runtime.h>
#include <cuda_fp16.h>
#include <cstdint>

// ============================================================================
// out[8192,512] = feats @ W^T + bias,  feats[b] = [x (128), x_i*x_j i<=j (8256)]
// K = 8384. FP16x3 (Markidis split) mma.sync GEMM, warp-specialized.
// R10: 3-stage B ring + 2-stage A ring, producer runs one tile ahead so
// cp.async latency is off the critical path.
// ============================================================================
static constexpr int DIM    = 128;
static constexpr int NQUAD  = 8256;
static constexpr int NFEAT  = 8384;
static constexpr int BATCH  = 8192;
static constexpr int NOUT   = 512;
static constexpr int KPW    = NFEAT / 2;          // 4192 half2 words per W row

static constexpr int TM = 128;
static constexpr int TN = 256;
static constexpr int TK = 32;                     // 16 half2 words
static constexpr int NKT = NFEAT / TK;            // 262
static constexpr int THREADS = 640;               // 16 consumer + 4 producer warps
static constexpr int NCONS   = 512;

static constexpr int STRW = 20;                   // row pitch (bank permutation)

// SMEM word layout
static constexpr int XT_OFF   = 0;                // fp32 x^T tile, 128 x 132
static constexpr int XT_STRIDE= 132;
static constexpr int AW_OFF   = XT_OFF + DIM * XT_STRIDE;        // 16896
static constexpr int A_COMP   = TM * STRW;                        // 2560
static constexpr int A_STAGE  = 2 * A_COMP;                       // hi+lo = 5120
static constexpr int BW_OFF   = AW_OFF + 2 * A_STAGE;             // 27136 (2 A stages)
static constexpr int B_COMP   = TN * STRW;                        // 5120
static constexpr int B_STAGE  = 2 * B_COMP;                       // 10240
static constexpr int SMEM_WORDS = BW_OFF + 3 * B_STAGE;           // 57856 (3 B stages)
static constexpr int SMEM_BYTES = SMEM_WORDS * 4;                 // 231424 (< 227KB cap)

// Named barriers: full[u%3] = 1..3, emptyA[u%2] = 4..5, emptyB[u%3] = 6..8
#define BAR_SYNC(id)   asm volatile("bar.sync %0, %1;"   :: "r"(id), "r"(THREADS) : "memory")
#define BAR_ARRIVE(id) asm volatile("bar.arrive %0, %1;" :: "r"(id), "r"(THREADS) : "memory")

// ============================================================================
// Device scratch: split weights (half2-packed hi/lo) + pair LUT
// ============================================================================
__device__ __align__(16) uint32_t g_whi[NOUT * KPW];   // 8.58 MB
__device__ __align__(16) uint32_t g_wlo[NOUT * KPW];   // 8.58 MB
__device__ __align__(16) unsigned short g_pairs[NQUAD];

__device__ __forceinline__ uint32_t pack_h2(__half lo16, __half hi16) {
    return (uint32_t)__half_as_ushort(lo16) | ((uint32_t)__half_as_ushort(hi16) << 16);
}
__device__ __forceinline__ void split_f32(float v, __half& h, __half& l) {
    h = __float2half_rn(v);
    l = __float2half_rn(v - __half2float(h));
}
__device__ __forceinline__ int pair_off(int i) { return DIM * i - (i * (i - 1)) / 2; }

__global__ void init_kernel(const float* __restrict__ w) {
    int gidx = blockIdx.x * 256 + threadIdx.x;
    if (gidx < NQUAD) {
        int q = gidx;
        int i = (int)((257.0f - sqrtf(66049.0f - 8.0f * (float)q)) * 0.5f);
        if (i < 0) i = 0;
        if (i > DIM - 1) i = DIM - 1;
        while (i > 0 && pair_off(i) > q) i--;
        while (i < DIM - 1 && pair_off(i + 1) <= q) i++;
        int j = i + (q - pair_off(i));
        g_pairs[q] = (unsigned short)((i << 8) | j);
    }
    int total = NOUT * KPW;
    for (int idx = gidx; idx < total; idx += gridDim.x * 256) {
        float2 v = *reinterpret_cast<const float2*>(w + 2 * (size_t)idx);
        __half h0, l0, h1, l1;
        split_f32(v.x, h0, l0);
        split_f32(v.y, h1, l1);
        g_whi[idx] = pack_h2(h0, h1);
        g_wlo[idx] = pack_h2(l0, l1);
    }
}

// ============================================================================
// helpers
// ============================================================================
__device__ __forceinline__ uint32_t smem_u32(const void* p) {
    uint32_t a;
    asm("{ .reg .u64 t; cvta.to.shared.u64 t, %1; cvt.u32.u64 %0, t; }" : "=r"(a) : "l"(p));
    return a;
}
__device__ __forceinline__ void cp_async16(uint32_t dst, const void* src) {
    asm volatile("cp.async.cg.shared.global [%0], [%1], 16;" :: "r"(dst), "l"(src) : "memory");
}
__device__ __forceinline__ void cp_commit() { asm volatile("cp.async.commit_group;" ::: "memory"); }
template <int N>
__device__ __forceinline__ void cp_wait() { asm volatile("cp.async.wait_group %0;" :: "n"(N) : "memory"); }

__device__ __forceinline__ void ldsm_x4(uint32_t& r0, uint32_t& r1, uint32_t& r2,
                                        uint32_t& r3, uint32_t addr) {
    asm volatile("ldmatrix.sync.aligned.m8n8.x4.shared.b16 {%0,%1,%2,%3}, [%4];"
                 : "=r"(r0), "=r"(r1), "=r"(r2), "=r"(r3) : "r"(addr));
}

__device__ __forceinline__ void mma_f16(float d[4], const uint32_t a[4], const uint32_t b[2]) {
    asm volatile(
        "mma.sync.aligned.m16n8k16.row.col.f32.f16.f16.f32 "
        "{%0,%1,%2,%3}, {%4,%5,%6,%7}, {%8,%9}, {%0,%1,%2,%3};"
        : "+f"(d[0]), "+f"(d[1]), "+f"(d[2]), "+f"(d[3])
        : "r"(a[0]), "r"(a[1]), "r"(a[2]), "r"(a[3]), "r"(b[0]), "r"(b[1]));
}

// ============================================================================
// Fused polynomial-feature GEMM (fp16x3, warp-spec, lookahead pipeline)
// ============================================================================
__global__ void __launch_bounds__(THREADS, 1)
poly_gemm_kernel(const float* __restrict__ x,
                 const float* __restrict__ bias,
                 float* __restrict__ out) {
    extern __shared__ float smemf[];
    uint32_t* smemw = reinterpret_cast<uint32_t*>(smemf);
    float* XT = smemf + XT_OFF;
    const uint32_t sb = smem_u32(smemf);

    const int tid  = threadIdx.x;
    const int lane = tid & 31;
    const int warp = tid >> 5;

    const int m0 = (int)(blockIdx.x >> 1) * TM;
    const int n0 = (int)(blockIdx.x & 1) * TN;

    // ---------------- prologue: xT tile ----------------
    for (int idx = tid; idx < TM * DIM; idx += THREADS) {
        int r = idx >> 7, c = idx & 127;
        XT[c * XT_STRIDE + r] = x[(size_t)(m0 + r) * DIM + c];
    }
    __syncthreads();

    if (warp >= 16) {
        // =================== PRODUCER (4 warps, 128 threads) ===================
        const int pid = tid - NCONS;        // 0..127
        const int pp  = pid & 15;           // k-pair within tile
        const int rb  = (pid >> 4) * 16;    // 16 rows per thread

        auto issue_B = [&](int t) {
            uint32_t dst0 = sb + (uint32_t)(BW_OFF + (t % 3) * B_STAGE) * 4u;
            const uint32_t* srch = g_whi + (size_t)n0 * KPW + t * 16;
            const uint32_t* srcl = g_wlo + (size_t)n0 * KPW + t * 16;
#pragma unroll
            for (int i = 0; i < 16; i++) {
                int c    = pid + i * 128;      // 0..2047
                int comp = c >> 10;
                int cc   = c & 1023;
                int row  = cc >> 2, qw = cc & 3;
                const uint32_t* src = (comp ? srcl : srch) + (size_t)row * KPW + qw * 4;
                cp_async16(dst0 + (uint32_t)(comp * B_COMP + row * STRW + qw * 4) * 4u, src);
            }
            cp_commit();
        };

        auto produce_A = [&](int t) {
            int kg = t * TK + 2 * pp;
            float v0[16], v1[16];
            if (kg < DIM) {
#pragma unroll
                for (int b = 0; b < 4; b++) {
                    float4 a0 = *(const float4*)(XT + (kg + 0) * XT_STRIDE + rb + 4 * b);
                    float4 b0 = *(const float4*)(XT + (kg + 1) * XT_STRIDE + rb + 4 * b);
                    v0[4*b+0]=a0.x; v0[4*b+1]=a0.y; v0[4*b+2]=a0.z; v0[4*b+3]=a0.w;
                    v1[4*b+0]=b0.x; v1[4*b+1]=b0.y; v1[4*b+2]=b0.z; v1[4*b+3]=b0.w;
                }
            } else {
                int q = kg - DIM;   // even -> aligned LUT read
                uint32_t pr = *reinterpret_cast<const uint32_t*>(&g_pairs[q]);
                int i0 = (pr >> 8) & 255, j0 = pr & 255;
                int i1 = (pr >> 24) & 255, j1 = (pr >> 16) & 255;
#pragma unroll
                for (int b = 0; b < 4; b++) {
                    float4 xa = *(const float4*)(XT + i0 * XT_STRIDE + rb + 4 * b);
                    float4 xb = *(const float4*)(XT + j0 * XT_STRIDE + rb + 4 * b);
                    float4 xc = *(const float4*)(XT + i1 * XT_STRIDE + rb + 4 * b);
                    float4 xd = *(const float4*)(XT + j1 * XT_STRIDE + rb + 4 * b);
                    v0[4*b+0]=xa.x*xb.x; v0[4*b+1]=xa.y*xb.y;
                    v0[4*b+2]=xa.z*xb.z; v0[4*b+3]=xa.w*xb.w;
                    v1[4*b+0]=xc.x*xd.x; v1[4*b+1]=xc.y*xd.y;
                    v1[4*b+2]=xc.z*xd.z; v1[4*b+3]=xc.w*xd.w;
                }
            }
            uint32_t* Ah = smemw + AW_OFF + (t & 1) * A_STAGE + rb * STRW + pp;
            uint32_t* Al = Ah + A_COMP;
#pragma unroll
            for (int r = 0; r < 16; r++) {
                __half h0, l0, h1, l1;
                split_f32(v0[r], h0, l0);
                split_f32(v1[r], h1, l1);
                Ah[r * STRW] = pack_h2(h0, h1);
                Al[r * STRW] = pack_h2(l0, l1);
            }
        };

        // prologue: fill tile 0 (stage free)
        issue_B(0);
        produce_A(0);

#pragma unroll 1
        for (int u = 0; u < NKT; ++u) {
            int v = u + 1;
            if (v < NKT) {
                if (v >= 2) BAR_SYNC(4 + (v & 1));     // emptyA: consumer done A[v-2]
                if (v >= 3) BAR_SYNC(6 + (v % 3));     // emptyB: consumer done B[v-3]
                issue_B(v);
                produce_A(v);
                cp_wait<1>();   // B[u] complete (B[v] may still fly)
            } else {
                cp_wait<0>();   // drain: B[u] complete
            }
            BAR_ARRIVE(1 + (u % 3));                   // publish full[u]
        }
    } else {
        // =================== CONSUMER (16 warps, 512 threads) ===================
        const int mw = warp >> 2;           // 0..3  rows mw*32
        const int nw = warp & 3;            // 0..3  cols nw*64

        float d[2][8][4];
#pragma unroll
        for (int a = 0; a < 2; a++)
#pragma unroll
            for (int b = 0; b < 8; b++)
#pragma unroll
                for (int c = 0; c < 4; c++) d[a][b][c] = 0.0f;

        const int a_lane_w = (lane & 15) * STRW + (lane >> 4) * 4;
        const int b_lane_w = ((lane & 7) + ((lane >> 4) & 1) * 8) * STRW + ((lane >> 3) & 1) * 4;

#pragma unroll 1
        for (int u = 0; u < NKT; ++u) {
            BAR_SYNC(1 + (u % 3));          // full[u]

            const uint32_t a_base = sb + (uint32_t)(AW_OFF + (u & 1) * A_STAGE
                                    + (mw * 32) * STRW + a_lane_w) * 4u;
            const uint32_t b_base = sb + (uint32_t)(BW_OFF + (u % 3) * B_STAGE
                                    + (nw * 64) * STRW + b_lane_w) * 4u;
#pragma unroll
            for (int ks = 0; ks < 2; ks++) {        // two k16 steps
                uint32_t ahi[2][4], alo[2][4];
#pragma unroll
                for (int mt = 0; mt < 2; mt++) {
                    uint32_t ap = a_base + (uint32_t)(mt * 16 * STRW + ks * 8) * 4u;
                    ldsm_x4(ahi[mt][0], ahi[mt][1], ahi[mt][2], ahi[mt][3], ap);
                    ldsm_x4(alo[mt][0], alo[mt][1], alo[mt][2], alo[mt][3],
                            ap + (uint32_t)A_COMP * 4u);
                }
#pragma unroll
                for (int p = 0; p < 4; p++) {       // 2 n-tiles per batch
                    uint32_t bhi[2][2], blo[2][2];
                    uint32_t bp = b_base + (uint32_t)(p * 16 * STRW + ks * 8) * 4u;
                    ldsm_x4(bhi[0][0], bhi[0][1], bhi[1][0], bhi[1][1], bp);
                    ldsm_x4(blo[0][0], blo[0][1], blo[1][0], blo[1][1],
                            bp + (uint32_t)B_COMP * 4u);
#pragma unroll
                    for (int mt = 0; mt < 2; mt++)
#pragma unroll
                        for (int n = 0; n < 2; n++)
                            mma_f16(d[mt][2*p+n], ahi[mt], bhi[n]);
#pragma unroll
                    for (int mt = 0; mt < 2; mt++)
#pragma unroll
                        for (int n = 0; n < 2; n++)
                            mma_f16(d[mt][2*p+n], ahi[mt], blo[n]);
#pragma unroll
                    for (int mt = 0; mt < 2; mt++)
#pragma unroll
                        for (int n = 0; n < 2; n++)
                            mma_f16(d[mt][2*p+n], alo[mt], bhi[n]);
                }
            }
            BAR_ARRIVE(4 + (u & 1));        // emptyA[u]
            BAR_ARRIVE(6 + (u % 3));        // emptyB[u]
        }

        // ---------------- epilogue (bias straight from gmem/L2) ----------------
        const int g  = lane >> 2;
        const int tg = lane & 3;
#pragma unroll
        for (int mt = 0; mt < 2; mt++) {
            int row = m0 + mw * 32 + mt * 16 + g;
#pragma unroll
            for (int nt = 0; nt < 8; nt++) {
                int col = n0 + nw * 64 + nt * 8 + tg * 2;
                float2 bv = *(const float2*)(bias + col);
                float2 o0 = { d[mt][nt][0] + bv.x, d[mt][nt][1] + bv.y };
                float2 o1 = { d[mt][nt][2] + bv.x, d[mt][nt][3] + bv.y };
                *(float2*)(out + (size_t)row * NOUT + col)       = o0;
                *(float2*)(out + (size_t)(row + 8) * NOUT + col) = o1;
            }
        }
    }
}

// ============================================================================
// Host launch
// ============================================================================
extern "C" void kernel_launch(void* const* d_in, const int* in_sizes, int n_in,
                              void* d_out, int out_size) {
    const float* x    = (const float*)d_in[0];
    const float* w    = (const float*)d_in[1];
    const float* bias = (const float*)d_in[2];
    float* out        = (float*)d_out;

    cudaFuncSetAttribute(poly_gemm_kernel,
                         cudaFuncAttributeMaxDynamicSharedMemorySize, SMEM_BYTES);

    init_kernel<<<1184, 256>>>(w);
    poly_gemm_kernel<<<(BATCH / TM) * (NOUT / TN), THREADS, SMEM_BYTES>>>(x, bias, out);
}

// round 11
// speedup vs baseline: 3.9308x; 1.2450x over previous
#include <cuda_runtime.h>
#include <cuda_fp16.h>
#include <cstdint>

// ============================================================================
// out[8192,512] = feats @ W^T + bias,  feats[b] = [x (128), x_i*x_j i<=j (8256)]
// K = 8384. FP16x3 (Markidis split) mma.sync GEMM, warp-specialized.
// R11: fixed lookahead pipeline — full[u] published the moment B[u] lands;
// next-tile A production / B issue happen AFTER publication.
// ============================================================================
static constexpr int DIM    = 128;
static constexpr int NQUAD  = 8256;
static constexpr int NFEAT  = 8384;
static constexpr int BATCH  = 8192;
static constexpr int NOUT   = 512;
static constexpr int KPW    = NFEAT / 2;          // 4192 half2 words per W row

static constexpr int TM = 128;
static constexpr int TN = 256;
static constexpr int TK = 32;                     // 16 half2 words
static constexpr int NKT = NFEAT / TK;            // 262
static constexpr int THREADS = 640;               // 16 consumer + 4 producer warps
static constexpr int NCONS   = 512;

static constexpr int STRW = 20;                   // row pitch (bank permutation)

// SMEM word layout
static constexpr int XT_OFF   = 0;                // fp32 x^T tile, 128 x 132
static constexpr int XT_STRIDE= 132;
static constexpr int AW_OFF   = XT_OFF + DIM * XT_STRIDE;        // 16896
static constexpr int A_COMP   = TM * STRW;                        // 2560
static constexpr int A_STAGE  = 2 * A_COMP;                       // hi+lo = 5120
static constexpr int BW_OFF   = AW_OFF + 2 * A_STAGE;             // 27136 (2 A stages)
static constexpr int B_COMP   = TN * STRW;                        // 5120
static constexpr int B_STAGE  = 2 * B_COMP;                       // 10240
static constexpr int SMEM_WORDS = BW_OFF + 3 * B_STAGE;           // 57856 (3 B stages)
static constexpr int SMEM_BYTES = SMEM_WORDS * 4;                 // 231424

// Named barriers: full[u%3] = 1..3, emptyA[u%2] = 4..5, emptyB[u%3] = 6..8
#define BAR_SYNC(id)   asm volatile("bar.sync %0, %1;"   :: "r"(id), "r"(THREADS) : "memory")
#define BAR_ARRIVE(id) asm volatile("bar.arrive %0, %1;" :: "r"(id), "r"(THREADS) : "memory")

// ============================================================================
// Device scratch: split weights (half2-packed hi/lo) + pair LUT
// ============================================================================
__device__ __align__(16) uint32_t g_whi[NOUT * KPW];   // 8.58 MB
__device__ __align__(16) uint32_t g_wlo[NOUT * KPW];   // 8.58 MB
__device__ __align__(16) unsigned short g_pairs[NQUAD];

__device__ __forceinline__ uint32_t pack_h2(__half lo16, __half hi16) {
    return (uint32_t)__half_as_ushort(lo16) | ((uint32_t)__half_as_ushort(hi16) << 16);
}
__device__ __forceinline__ void split_f32(float v, __half& h, __half& l) {
    h = __float2half_rn(v);
    l = __float2half_rn(v - __half2float(h));
}
__device__ __forceinline__ int pair_off(int i) { return DIM * i - (i * (i - 1)) / 2; }

__global__ void init_kernel(const float* __restrict__ w) {
    int gidx = blockIdx.x * 256 + threadIdx.x;
    if (gidx < NQUAD) {
        int q = gidx;
        int i = (int)((257.0f - sqrtf(66049.0f - 8.0f * (float)q)) * 0.5f);
        if (i < 0) i = 0;
        if (i > DIM - 1) i = DIM - 1;
        while (i > 0 && pair_off(i) > q) i--;
        while (i < DIM - 1 && pair_off(i + 1) <= q) i++;
        int j = i + (q - pair_off(i));
        g_pairs[q] = (unsigned short)((i << 8) | j);
    }
    int total = NOUT * KPW;
    for (int idx = gidx; idx < total; idx += gridDim.x * 256) {
        float2 v = *reinterpret_cast<const float2*>(w + 2 * (size_t)idx);
        __half h0, l0, h1, l1;
        split_f32(v.x, h0, l0);
        split_f32(v.y, h1, l1);
        g_whi[idx] = pack_h2(h0, h1);
        g_wlo[idx] = pack_h2(l0, l1);
    }
}

// ============================================================================
// helpers
// ============================================================================
__device__ __forceinline__ uint32_t smem_u32(const void* p) {
    uint32_t a;
    asm("{ .reg .u64 t; cvta.to.shared.u64 t, %1; cvt.u32.u64 %0, t; }" : "=r"(a) : "l"(p));
    return a;
}
__device__ __forceinline__ void cp_async16(uint32_t dst, const void* src) {
    asm volatile("cp.async.cg.shared.global [%0], [%1], 16;" :: "r"(dst), "l"(src) : "memory");
}
__device__ __forceinline__ void cp_commit() { asm volatile("cp.async.commit_group;" ::: "memory"); }
template <int N>
__device__ __forceinline__ void cp_wait() { asm volatile("cp.async.wait_group %0;" :: "n"(N) : "memory"); }

__device__ __forceinline__ void ldsm_x4(uint32_t& r0, uint32_t& r1, uint32_t& r2,
                                        uint32_t& r3, uint32_t addr) {
    asm volatile("ldmatrix.sync.aligned.m8n8.x4.shared.b16 {%0,%1,%2,%3}, [%4];"
                 : "=r"(r0), "=r"(r1), "=r"(r2), "=r"(r3) : "r"(addr));
}

__device__ __forceinline__ void mma_f16(float d[4], const uint32_t a[4], const uint32_t b[2]) {
    asm volatile(
        "mma.sync.aligned.m16n8k16.row.col.f32.f16.f16.f32 "
        "{%0,%1,%2,%3}, {%4,%5,%6,%7}, {%8,%9}, {%0,%1,%2,%3};"
        : "+f"(d[0]), "+f"(d[1]), "+f"(d[2]), "+f"(d[3])
        : "r"(a[0]), "r"(a[1]), "r"(a[2]), "r"(a[3]), "r"(b[0]), "r"(b[1]));
}

// ============================================================================
// Fused polynomial-feature GEMM (fp16x3, warp-spec, corrected lookahead)
// ============================================================================
__global__ void __launch_bounds__(THREADS, 1)
poly_gemm_kernel(const float* __restrict__ x,
                 const float* __restrict__ bias,
                 float* __restrict__ out) {
    extern __shared__ float smemf[];
    uint32_t* smemw = reinterpret_cast<uint32_t*>(smemf);
    float* XT = smemf + XT_OFF;
    const uint32_t sb = smem_u32(smemf);

    const int tid  = threadIdx.x;
    const int lane = tid & 31;
    const int warp = tid >> 5;

    const int m0 = (int)(blockIdx.x >> 1) * TM;
    const int n0 = (int)(blockIdx.x & 1) * TN;

    // ---------------- prologue: xT tile ----------------
    for (int idx = tid; idx < TM * DIM; idx += THREADS) {
        int r = idx >> 7, c = idx & 127;
        XT[c * XT_STRIDE + r] = x[(size_t)(m0 + r) * DIM + c];
    }
    __syncthreads();

    if (warp >= 16) {
        // =================== PRODUCER (4 warps, 128 threads) ===================
        const int pid = tid - NCONS;        // 0..127
        const int pp  = pid & 15;           // k-pair within tile
        const int rb  = (pid >> 4) * 16;    // 16 rows per thread

        auto issue_B = [&](int t) {
            uint32_t dst0 = sb + (uint32_t)(BW_OFF + (t % 3) * B_STAGE) * 4u;
            const uint32_t* srch = g_whi + (size_t)n0 * KPW + t * 16;
            const uint32_t* srcl = g_wlo + (size_t)n0 * KPW + t * 16;
#pragma unroll
            for (int i = 0; i < 16; i++) {
                int c    = pid + i * 128;      // 0..2047
                int comp = c >> 10;
                int cc   = c & 1023;
                int row  = cc >> 2, qw = cc & 3;
                const uint32_t* src = (comp ? srcl : srch) + (size_t)row * KPW + qw * 4;
                cp_async16(dst0 + (uint32_t)(comp * B_COMP + row * STRW + qw * 4) * 4u, src);
            }
            cp_commit();
        };

        auto produce_A = [&](int t) {
            int kg = t * TK + 2 * pp;
            float v0[16], v1[16];
            if (kg < DIM) {
#pragma unroll
                for (int b = 0; b < 4; b++) {
                    float4 a0 = *(const float4*)(XT + (kg + 0) * XT_STRIDE + rb + 4 * b);
                    float4 b0 = *(const float4*)(XT + (kg + 1) * XT_STRIDE + rb + 4 * b);
                    v0[4*b+0]=a0.x; v0[4*b+1]=a0.y; v0[4*b+2]=a0.z; v0[4*b+3]=a0.w;
                    v1[4*b+0]=b0.x; v1[4*b+1]=b0.y; v1[4*b+2]=b0.z; v1[4*b+3]=b0.w;
                }
            } else {
                int q = kg - DIM;   // even -> aligned LUT read
                uint32_t pr = *reinterpret_cast<const uint32_t*>(&g_pairs[q]);
                int i0 = (pr >> 8) & 255, j0 = pr & 255;
                int i1 = (pr >> 24) & 255, j1 = (pr >> 16) & 255;
#pragma unroll
                for (int b = 0; b < 4; b++) {
                    float4 xa = *(const float4*)(XT + i0 * XT_STRIDE + rb + 4 * b);
                    float4 xb = *(const float4*)(XT + j0 * XT_STRIDE + rb + 4 * b);
                    float4 xc = *(const float4*)(XT + i1 * XT_STRIDE + rb + 4 * b);
                    float4 xd = *(const float4*)(XT + j1 * XT_STRIDE + rb + 4 * b);
                    v0[4*b+0]=xa.x*xb.x; v0[4*b+1]=xa.y*xb.y;
                    v0[4*b+2]=xa.z*xb.z; v0[4*b+3]=xa.w*xb.w;
                    v1[4*b+0]=xc.x*xd.x; v1[4*b+1]=xc.y*xd.y;
                    v1[4*b+2]=xc.z*xd.z; v1[4*b+3]=xc.w*xd.w;
                }
            }
            uint32_t* Ah = smemw + AW_OFF + (t & 1) * A_STAGE + rb * STRW + pp;
            uint32_t* Al = Ah + A_COMP;
#pragma unroll
            for (int r = 0; r < 16; r++) {
                __half h0, l0, h1, l1;
                split_f32(v0[r], h0, l0);
                split_f32(v1[r], h1, l1);
                Ah[r * STRW] = pack_h2(h0, h1);
                Al[r * STRW] = pack_h2(l0, l1);
            }
        };

        // prologue: tile 0 data + B[1] in flight
        issue_B(0);
        produce_A(0);
        issue_B(1);

#pragma unroll 1
        for (int u = 0; u < NKT; ++u) {
            // B[u] complete (B[u+1] may still fly); A[u] already produced
            if (u + 1 < NKT) cp_wait<1>();
            else             cp_wait<0>();
            BAR_ARRIVE(1 + (u % 3));               // publish full[u] IMMEDIATELY

            int an = u + 1;                        // produce A for next tile
            if (an < NKT) {
                if (an >= 2) BAR_SYNC(4 + (an & 1));      // emptyA
                produce_A(an);
            }
            int bn = u + 2;                        // keep one B-tile in flight
            if (bn < NKT) {
                if (bn >= 3) BAR_SYNC(6 + (bn % 3));      // emptyB
                issue_B(bn);
            }
        }
    } else {
        // =================== CONSUMER (16 warps, 512 threads) ===================
        const int mw = warp >> 2;           // 0..3  rows mw*32
        const int nw = warp & 3;            // 0..3  cols nw*64

        float d[2][8][4];
#pragma unroll
        for (int a = 0; a < 2; a++)
#pragma unroll
            for (int b = 0; b < 8; b++)
#pragma unroll
                for (int c = 0; c < 4; c++) d[a][b][c] = 0.0f;

        const int a_lane_w = (lane & 15) * STRW + (lane >> 4) * 4;
        const int b_lane_w = ((lane & 7) + ((lane >> 4) & 1) * 8) * STRW + ((lane >> 3) & 1) * 4;

#pragma unroll 1
        for (int u = 0; u < NKT; ++u) {
            BAR_SYNC(1 + (u % 3));          // full[u]

            const uint32_t a_base = sb + (uint32_t)(AW_OFF + (u & 1) * A_STAGE
                                    + (mw * 32) * STRW + a_lane_w) * 4u;
            const uint32_t b_base = sb + (uint32_t)(BW_OFF + (u % 3) * B_STAGE
                                    + (nw * 64) * STRW + b_lane_w) * 4u;
#pragma unroll
            for (int ks = 0; ks < 2; ks++) {        // two k16 steps
                uint32_t ahi[2][4], alo[2][4];
#pragma unroll
                for (int mt = 0; mt < 2; mt++) {
                    uint32_t ap = a_base + (uint32_t)(mt * 16 * STRW + ks * 8) * 4u;
                    ldsm_x4(ahi[mt][0], ahi[mt][1], ahi[mt][2], ahi[mt][3], ap);
                    ldsm_x4(alo[mt][0], alo[mt][1], alo[mt][2], alo[mt][3],
                            ap + (uint32_t)A_COMP * 4u);
                }
#pragma unroll
                for (int p = 0; p < 4; p++) {       // 2 n-tiles per batch
                    uint32_t bhi[2][2], blo[2][2];
                    uint32_t bp = b_base + (uint32_t)(p * 16 * STRW + ks * 8) * 4u;
                    ldsm_x4(bhi[0][0], bhi[0][1], bhi[1][0], bhi[1][1], bp);
                    ldsm_x4(blo[0][0], blo[0][1], blo[1][0], blo[1][1],
                            bp + (uint32_t)B_COMP * 4u);
#pragma unroll
                    for (int mt = 0; mt < 2; mt++)
#pragma unroll
                        for (int n = 0; n < 2; n++)
                            mma_f16(d[mt][2*p+n], ahi[mt], bhi[n]);
#pragma unroll
                    for (int mt = 0; mt < 2; mt++)
#pragma unroll
                        for (int n = 0; n < 2; n++)
                            mma_f16(d[mt][2*p+n], ahi[mt], blo[n]);
#pragma unroll
                    for (int mt = 0; mt < 2; mt++)
#pragma unroll
                        for (int n = 0; n < 2; n++)
                            mma_f16(d[mt][2*p+n], alo[mt], bhi[n]);
                }
            }
            BAR_ARRIVE(4 + (u & 1));        // emptyA[u]
            BAR_ARRIVE(6 + (u % 3));        // emptyB[u]
        }

        // ---------------- epilogue ----------------
        const int g  = lane >> 2;
        const int tg = lane & 3;
#pragma unroll
        for (int mt = 0; mt < 2; mt++) {
            int row = m0 + mw * 32 + mt * 16 + g;
#pragma unroll
            for (int nt = 0; nt < 8; nt++) {
                int col = n0 + nw * 64 + nt * 8 + tg * 2;
                float2 bv = *(const float2*)(bias + col);
                float2 o0 = { d[mt][nt][0] + bv.x, d[mt][nt][1] + bv.y };
                float2 o1 = { d[mt][nt][2] + bv.x, d[mt][nt][3] + bv.y };
                *(float2*)(out + (size_t)row * NOUT + col)       = o0;
                *(float2*)(out + (size_t)(row + 8) * NOUT + col) = o1;
            }
        }
    }
}

// ============================================================================
// Host launch
// ============================================================================
extern "C" void kernel_launch(void* const* d_in, const int* in_sizes, int n_in,
                              void* d_out, int out_size) {
    const float* x    = (const float*)d_in[0];
    const float* w    = (const float*)d_in[1];
    const float* bias = (const float*)d_in[2];
    float* out        = (float*)d_out;

    cudaFuncSetAttribute(poly_gemm_kernel,
                         cudaFuncAttributeMaxDynamicSharedMemorySize, SMEM_BYTES);

    init_kernel<<<1184, 256>>>(w);
    poly_gemm_kernel<<<(BATCH / TM) * (NOUT / TN), THREADS, SMEM_BYTES>>>(x, bias, out);
}

// round 12
// speedup vs baseline: 4.7744x; 1.2146x over previous
#include <cuda_runtime.h>
#include <cuda_fp16.h>
#include <cstdint>

// ============================================================================
// out[8192,512] = feats @ W^T + bias,  feats[b] = [x (128), x_i*x_j i<=j (8256)]
// K = 8384. FP16x3 (Markidis split) mma.sync GEMM, warp-specialized.
// R12: mbarrier pipeline — consumer warps proceed independently (no full-CTA
// named-barrier convergence per tile). cp.async completion folded into the
// full barrier via cp.async.mbarrier.arrive.
// ============================================================================
static constexpr int DIM    = 128;
static constexpr int NQUAD  = 8256;
static constexpr int NFEAT  = 8384;
static constexpr int BATCH  = 8192;
static constexpr int NOUT   = 512;
static constexpr int KPW    = NFEAT / 2;          // 4192 half2 words per W row

static constexpr int TM = 128;
static constexpr int TN = 256;
static constexpr int TK = 32;                     // 16 half2 words
static constexpr int NKT = NFEAT / TK;            // 262
static constexpr int THREADS = 640;               // 16 consumer + 4 producer warps
static constexpr int NCONS   = 512;

static constexpr int STRW = 20;                   // row pitch (bank permutation)

// SMEM word layout (2 stages A + 2 stages B, as in R8)
static constexpr int XT_OFF   = 0;                // fp32 x^T tile, 128 x 132
static constexpr int XT_STRIDE= 132;
static constexpr int AW_OFF   = XT_OFF + DIM * XT_STRIDE;        // 16896
static constexpr int A_COMP   = TM * STRW;                        // 2560
static constexpr int A_STAGE  = 2 * A_COMP;                       // hi+lo = 5120
static constexpr int BW_OFF   = AW_OFF + 2 * A_STAGE;             // 27136
static constexpr int B_COMP   = TN * STRW;                        // 5120
static constexpr int B_STAGE  = 2 * B_COMP;                       // 10240
static constexpr int MB_OFF   = BW_OFF + 2 * B_STAGE;             // 47616 (words)
static constexpr int SMEM_WORDS = MB_OFF + 8;                     // 4 mbarriers x 8B
static constexpr int SMEM_BYTES = SMEM_WORDS * 4;                 // 190496

// mbarrier byte offsets from smem base
// full[s]  = MB_OFF*4 + s*8   (expected: 128 producer arrives + cp-async inc/dec)
// empty[s] = MB_OFF*4 + 16 + s*8  (expected: 512 consumer arrives)

// ============================================================================
// Device scratch: split weights (half2-packed hi/lo) + pair LUT
// ============================================================================
__device__ __align__(16) uint32_t g_whi[NOUT * KPW];   // 8.58 MB
__device__ __align__(16) uint32_t g_wlo[NOUT * KPW];   // 8.58 MB
__device__ __align__(16) unsigned short g_pairs[NQUAD];

__device__ __forceinline__ uint32_t pack_h2(__half lo16, __half hi16) {
    return (uint32_t)__half_as_ushort(lo16) | ((uint32_t)__half_as_ushort(hi16) << 16);
}
__device__ __forceinline__ void split_f32(float v, __half& h, __half& l) {
    h = __float2half_rn(v);
    l = __float2half_rn(v - __half2float(h));
}
__device__ __forceinline__ int pair_off(int i) { return DIM * i - (i * (i - 1)) / 2; }

__global__ void init_kernel(const float* __restrict__ w) {
    int gidx = blockIdx.x * 256 + threadIdx.x;
    if (gidx < NQUAD) {
        int q = gidx;
        int i = (int)((257.0f - sqrtf(66049.0f - 8.0f * (float)q)) * 0.5f);
        if (i < 0) i = 0;
        if (i > DIM - 1) i = DIM - 1;
        while (i > 0 && pair_off(i) > q) i--;
        while (i < DIM - 1 && pair_off(i + 1) <= q) i++;
        int j = i + (q - pair_off(i));
        g_pairs[q] = (unsigned short)((i << 8) | j);
    }
    int total = NOUT * KPW;
    for (int idx = gidx; idx < total; idx += gridDim.x * 256) {
        float2 v = *reinterpret_cast<const float2*>(w + 2 * (size_t)idx);
        __half h0, l0, h1, l1;
        split_f32(v.x, h0, l0);
        split_f32(v.y, h1, l1);
        g_whi[idx] = pack_h2(h0, h1);
        g_wlo[idx] = pack_h2(l0, l1);
    }
}

// ============================================================================
// helpers
// ============================================================================
__device__ __forceinline__ uint32_t smem_u32(const void* p) {
    uint32_t a;
    asm("{ .reg .u64 t; cvta.to.shared.u64 t, %1; cvt.u32.u64 %0, t; }" : "=r"(a) : "l"(p));
    return a;
}
__device__ __forceinline__ void cp_async16(uint32_t dst, const void* src) {
    asm volatile("cp.async.cg.shared.global [%0], [%1], 16;" :: "r"(dst), "l"(src) : "memory");
}
__device__ __forceinline__ void cp_async_mbar_arrive(uint32_t mbar) {
    asm volatile("cp.async.mbarrier.arrive.shared.b64 [%0];" :: "r"(mbar) : "memory");
}

#define MBARRIER_INIT(mbar, cnt) \
    asm volatile("mbarrier.init.shared.b64 [%0], %1;" :: "r"((uint32_t)(mbar)), "r"((uint32_t)(cnt)) : "memory")
#define MBARRIER_ARRIVE(mbar) \
    asm volatile("mbarrier.arrive.shared.b64 _, [%0];" :: "r"((uint32_t)(mbar)) : "memory")
#define MBARRIER_WAIT_PARITY(mbar, parity) do {                                   \
    uint32_t _m = (uint32_t)(mbar);                                               \
    uint32_t _p = (uint32_t)(parity);                                             \
    uint32_t _done;                                                               \
    asm volatile("{\n\t.reg .pred p;\n\t"                                        \
        "mbarrier.try_wait.parity.acquire.cta.shared::cta.b64 p, [%1], %2;\n\t"   \
        "selp.b32 %0, 1, 0, p;\n\t}"                                              \
        : "=r"(_done) : "r"(_m), "r"(_p) : "memory");                             \
    if (!_done) {                                                                 \
        asm volatile("{\n\t.reg .pred P1;\n\t"                                    \
            "WL_%=:\n\t"                                                          \
            "mbarrier.try_wait.parity.acquire.cta.shared::cta.b64 P1, [%0], %1, 0x989680;\n\t" \
            "@P1 bra.uni WD_%=;\n\t"                                              \
            "bra.uni WL_%=;\n\t"                                                  \
            "WD_%=:\n\t}"                                                         \
            :: "r"(_m), "r"(_p) : "memory");                                      \
    }                                                                             \
} while (0)

__device__ __forceinline__ void ldsm_x4(uint32_t& r0, uint32_t& r1, uint32_t& r2,
                                        uint32_t& r3, uint32_t addr) {
    asm volatile("ldmatrix.sync.aligned.m8n8.x4.shared.b16 {%0,%1,%2,%3}, [%4];"
                 : "=r"(r0), "=r"(r1), "=r"(r2), "=r"(r3) : "r"(addr));
}

__device__ __forceinline__ void mma_f16(float d[4], const uint32_t a[4], const uint32_t b[2]) {
    asm volatile(
        "mma.sync.aligned.m16n8k16.row.col.f32.f16.f16.f32 "
        "{%0,%1,%2,%3}, {%4,%5,%6,%7}, {%8,%9}, {%0,%1,%2,%3};"
        : "+f"(d[0]), "+f"(d[1]), "+f"(d[2]), "+f"(d[3])
        : "r"(a[0]), "r"(a[1]), "r"(a[2]), "r"(a[3]), "r"(b[0]), "r"(b[1]));
}

// ============================================================================
// Fused polynomial-feature GEMM (fp16x3, warp-spec, mbarrier pipeline)
// ============================================================================
__global__ void __launch_bounds__(THREADS, 1)
poly_gemm_kernel(const float* __restrict__ x,
                 const float* __restrict__ bias,
                 float* __restrict__ out) {
    extern __shared__ float smemf[];
    uint32_t* smemw = reinterpret_cast<uint32_t*>(smemf);
    float* XT = smemf + XT_OFF;
    const uint32_t sb = smem_u32(smemf);
    const uint32_t mb_full  = sb + (uint32_t)MB_OFF * 4u;        // +s*8
    const uint32_t mb_empty = sb + (uint32_t)MB_OFF * 4u + 16u;  // +s*8

    const int tid  = threadIdx.x;
    const int lane = tid & 31;
    const int warp = tid >> 5;

    const int m0 = (int)(blockIdx.x >> 1) * TM;
    const int n0 = (int)(blockIdx.x & 1) * TN;

    // ---------------- prologue: mbarriers + xT tile ----------------
    if (tid == 0) {
        MBARRIER_INIT(mb_full,       128);
        MBARRIER_INIT(mb_full + 8,   128);
        MBARRIER_INIT(mb_empty,      512);
        MBARRIER_INIT(mb_empty + 8,  512);
    }
    for (int idx = tid; idx < TM * DIM; idx += THREADS) {
        int r = idx >> 7, c = idx & 127;
        XT[c * XT_STRIDE + r] = x[(size_t)(m0 + r) * DIM + c];
    }
    __syncthreads();

    if (warp >= 16) {
        // =================== PRODUCER (4 warps, 128 threads) ===================
        const int pid = tid - NCONS;        // 0..127
        const int pp  = pid & 15;           // k-pair within tile
        const int rb  = (pid >> 4) * 16;    // 16 rows per thread

#pragma unroll 1
        for (int t = 0; t < NKT; ++t) {
            int s = t & 1;
            if (t >= 2) MBARRIER_WAIT_PARITY(mb_empty + s * 8, ((t >> 1) - 1) & 1);

            // ---- B tile: 16 cp.async16 per thread, completion -> full[s] ----
            {
                uint32_t dst0 = sb + (uint32_t)(BW_OFF + s * B_STAGE) * 4u;
                const uint32_t* srch = g_whi + (size_t)n0 * KPW + t * 16;
                const uint32_t* srcl = g_wlo + (size_t)n0 * KPW + t * 16;
#pragma unroll
                for (int i = 0; i < 16; i++) {
                    int c    = pid + i * 128;      // 0..2047
                    int comp = c >> 10;
                    int cc   = c & 1023;
                    int row  = cc >> 2, qw = cc & 3;
                    const uint32_t* src = (comp ? srcl : srch) + (size_t)row * KPW + qw * 4;
                    cp_async16(dst0 + (uint32_t)(comp * B_COMP + row * STRW + qw * 4) * 4u, src);
                }
                cp_async_mbar_arrive(mb_full + s * 8);
            }

            // ---- A tile: 2 k-columns x 16 rows per thread ----
            {
                int kg = t * TK + 2 * pp;
                float v0[16], v1[16];
                if (kg < DIM) {
#pragma unroll
                    for (int b = 0; b < 4; b++) {
                        float4 a0 = *(const float4*)(XT + (kg + 0) * XT_STRIDE + rb + 4 * b);
                        float4 b0 = *(const float4*)(XT + (kg + 1) * XT_STRIDE + rb + 4 * b);
                        v0[4*b+0]=a0.x; v0[4*b+1]=a0.y; v0[4*b+2]=a0.z; v0[4*b+3]=a0.w;
                        v1[4*b+0]=b0.x; v1[4*b+1]=b0.y; v1[4*b+2]=b0.z; v1[4*b+3]=b0.w;
                    }
                } else {
                    int q = kg - DIM;   // even -> aligned LUT read
                    uint32_t pr = *reinterpret_cast<const uint32_t*>(&g_pairs[q]);
                    int i0 = (pr >> 8) & 255, j0 = pr & 255;
                    int i1 = (pr >> 24) & 255, j1 = (pr >> 16) & 255;
#pragma unroll
                    for (int b = 0; b < 4; b++) {
                        float4 xa = *(const float4*)(XT + i0 * XT_STRIDE + rb + 4 * b);
                        float4 xb = *(const float4*)(XT + j0 * XT_STRIDE + rb + 4 * b);
                        float4 xc = *(const float4*)(XT + i1 * XT_STRIDE + rb + 4 * b);
                        float4 xd = *(const float4*)(XT + j1 * XT_STRIDE + rb + 4 * b);
                        v0[4*b+0]=xa.x*xb.x; v0[4*b+1]=xa.y*xb.y;
                        v0[4*b+2]=xa.z*xb.z; v0[4*b+3]=xa.w*xb.w;
                        v1[4*b+0]=xc.x*xd.x; v1[4*b+1]=xc.y*xd.y;
                        v1[4*b+2]=xc.z*xd.z; v1[4*b+3]=xc.w*xd.w;
                    }
                }
                uint32_t* Ah = smemw + AW_OFF + s * A_STAGE + rb * STRW + pp;
                uint32_t* Al = Ah + A_COMP;
#pragma unroll
                for (int r = 0; r < 16; r++) {
                    __half h0, l0, h1, l1;
                    split_f32(v0[r], h0, l0);
                    split_f32(v1[r], h1, l1);
                    Ah[r * STRW] = pack_h2(h0, h1);
                    Al[r * STRW] = pack_h2(l0, l1);
                }
            }

            MBARRIER_ARRIVE(mb_full + s * 8);   // STS done (release)
        }
    } else {
        // =================== CONSUMER (16 warps, 512 threads) ===================
        const int mw = warp >> 2;           // 0..3  rows mw*32
        const int nw = warp & 3;            // 0..3  cols nw*64

        float d[2][8][4];
#pragma unroll
        for (int a = 0; a < 2; a++)
#pragma unroll
            for (int b = 0; b < 8; b++)
#pragma unroll
                for (int c = 0; c < 4; c++) d[a][b][c] = 0.0f;

        const int a_lane_w = (lane & 15) * STRW + (lane >> 4) * 4;
        const int b_lane_w = ((lane & 7) + ((lane >> 4) & 1) * 8) * STRW + ((lane >> 3) & 1) * 4;

#pragma unroll 1
        for (int u = 0; u < NKT; ++u) {
            int s = u & 1;
            MBARRIER_WAIT_PARITY(mb_full + s * 8, (u >> 1) & 1);

            const uint32_t a_base = sb + (uint32_t)(AW_OFF + s * A_STAGE
                                    + (mw * 32) * STRW + a_lane_w) * 4u;
            const uint32_t b_base = sb + (uint32_t)(BW_OFF + s * B_STAGE
                                    + (nw * 64) * STRW + b_lane_w) * 4u;
#pragma unroll
            for (int ks = 0; ks < 2; ks++) {        // two k16 steps
                uint32_t ahi[2][4], alo[2][4];
#pragma unroll
                for (int mt = 0; mt < 2; mt++) {
                    uint32_t ap = a_base + (uint32_t)(mt * 16 * STRW + ks * 8) * 4u;
                    ldsm_x4(ahi[mt][0], ahi[mt][1], ahi[mt][2], ahi[mt][3], ap);
                    ldsm_x4(alo[mt][0], alo[mt][1], alo[mt][2], alo[mt][3],
                            ap + (uint32_t)A_COMP * 4u);
                }
#pragma unroll
                for (int p = 0; p < 4; p++) {       // 2 n-tiles per batch
                    uint32_t bhi[2][2], blo[2][2];
                    uint32_t bp = b_base + (uint32_t)(p * 16 * STRW + ks * 8) * 4u;
                    ldsm_x4(bhi[0][0], bhi[0][1], bhi[1][0], bhi[1][1], bp);
                    ldsm_x4(blo[0][0], blo[0][1], blo[1][0], blo[1][1],
                            bp + (uint32_t)B_COMP * 4u);
#pragma unroll
                    for (int mt = 0; mt < 2; mt++)
#pragma unroll
                        for (int n = 0; n < 2; n++)
                            mma_f16(d[mt][2*p+n], ahi[mt], bhi[n]);
#pragma unroll
                    for (int mt = 0; mt < 2; mt++)
#pragma unroll
                        for (int n = 0; n < 2; n++)
                            mma_f16(d[mt][2*p+n], ahi[mt], blo[n]);
#pragma unroll
                    for (int mt = 0; mt < 2; mt++)
#pragma unroll
                        for (int n = 0; n < 2; n++)
                            mma_f16(d[mt][2*p+n], alo[mt], bhi[n]);
                }
            }
            MBARRIER_ARRIVE(mb_empty + s * 8);
        }

        // ---------------- epilogue ----------------
        const int g  = lane >> 2;
        const int tg = lane & 3;
#pragma unroll
        for (int mt = 0; mt < 2; mt++) {
            int row = m0 + mw * 32 + mt * 16 + g;
#pragma unroll
            for (int nt = 0; nt < 8; nt++) {
                int col = n0 + nw * 64 + nt * 8 + tg * 2;
                float2 bv = *(const float2*)(bias + col);
                float2 o0 = { d[mt][nt][0] + bv.x, d[mt][nt][1] + bv.y };
                float2 o1 = { d[mt][nt][2] + bv.x, d[mt][nt][3] + bv.y };
                *(float2*)(out + (size_t)row * NOUT + col)       = o0;
                *(float2*)(out + (size_t)(row + 8) * NOUT + col) = o1;
            }
        }
    }
}

// ============================================================================
// Host launch
// ============================================================================
extern "C" void kernel_launch(void* const* d_in, const int* in_sizes, int n_in,
                              void* d_out, int out_size) {
    const float* x    = (const float*)d_in[0];
    const float* w    = (const float*)d_in[1];
    const float* bias = (const float*)d_in[2];
    float* out        = (float*)d_out;

    cudaFuncSetAttribute(poly_gemm_kernel,
                         cudaFuncAttributeMaxDynamicSharedMemorySize, SMEM_BYTES);

    init_kernel<<<1184, 256>>>(w);
    poly_gemm_kernel<<<(BATCH / TM) * (NOUT / TN), THREADS, SMEM_BYTES>>>(x, bias, out);
}